// round 12
// baseline (speedup 1.0000x reference)
#include <cuda_runtime.h>
#include <cooperative_groups.h>
#include <cstddef>

namespace cg = cooperative_groups;

// Problem constants (Attention_88811333746876)
#define BB   32
#define HSZ  512
#define CC   256
#define HWN  4096     // 64*64
#define AA   256

#define PX   64       // pixels per tile
#define CPB  8        // cluster CTAs per batch
#define TPC  8        // tiles per CTA (8*8*64 = 4096 px)

// Scratch (allocation-free rule: __device__ globals)
__device__ float g_v[BB * CC];

// ---------------------------------------------------------------------------
// Kernel 1 (front-end): per-batch CTA computes wh = h@W_h + b_h, then
// v = W_fm @ wh. One node replaces k_wh + k_v.
// (b_fm dropped: it shifts scores by a per-b constant -> softmax invariant)
// ---------------------------------------------------------------------------
__global__ void __launch_bounds__(256) k_front(const float* __restrict__ h_dec,
                                               const float* __restrict__ W_h,
                                               const float* __restrict__ W_fm,
                                               const float* __restrict__ b_h)
{
    __shared__ float h_s[HSZ];        // 2 KB
    __shared__ float wh_s[AA];        // 1 KB
    __shared__ float part[4][64];

    const int b = blockIdx.x;
    const int t = threadIdx.x;        // 256

    h_s[t]       = h_dec[b * HSZ + t];
    h_s[t + 256] = h_dec[b * HSZ + t + 256];
    __syncthreads();

    // ---- phase 1: wh[a] = sum_k h[k]*W_h[k,a] + b_h[a], k-split x4 ----
    const int kp = t >> 6;            // 0..3
    const int al = t & 63;
    const int k0 = kp * 128;
    for (int at = 0; at < 4; ++at) {
        const int a = at * 64 + al;
        float acc = 0.f;
#pragma unroll 8
        for (int k = k0; k < k0 + 128; ++k)
            acc += h_s[k] * W_h[k * AA + a];
        part[kp][al] = acc;
        __syncthreads();
        if (t < 64)
            wh_s[at * 64 + t] = part[0][t] + part[1][t] + part[2][t] + part[3][t]
                              + b_h[at * 64 + t];
        __syncthreads();              // before next tile overwrites part
    }

    // ---- phase 2: v[c] = sum_a W_fm[c,a]*wh[a], warp-per-row ----
    const int lane = t & 31;
    const int w    = t >> 5;          // 8 warps x 32 rows
    const float4* Wf4  = reinterpret_cast<const float4*>(W_fm);
    const float4* whs4 = reinterpret_cast<const float4*>(wh_s);
#pragma unroll 4
    for (int ci = 0; ci < 32; ++ci) {
        const int c = w * 32 + ci;
        float4 w0 = Wf4[c * 64 + lane];
        float4 w1 = Wf4[c * 64 + 32 + lane];
        float4 h0 = whs4[lane];
        float4 h1 = whs4[lane + 32];
        float acc = w0.x * h0.x + w0.y * h0.y + w0.z * h0.z + w0.w * h0.w
                  + w1.x * h1.x + w1.y * h1.y + w1.z * h1.z + w1.w * h1.w;
#pragma unroll
        for (int o = 16; o; o >>= 1) acc += __shfl_xor_sync(0xffffffffu, acc, o);
        if (lane == 0) g_v[b * CC + c] = acc;
    }
}

// ---------------------------------------------------------------------------
// Kernel 2: fused streaming pass + IN-CLUSTER combine.
// grid (B, 8), cluster (1, 8): the 8 CTAs of batch b form a cluster. Each CTA
// merges 8 tiles (64 px each) with online softmax (register-resident tile,
// 16 float4/thread). Final combine via DSMEM after cluster.sync(): each CTA
// reads peers' (m, s, acc) from distributed shared memory and writes its 32
// output channels. No trailing kernel, no global partials, no threadfence.
// ---------------------------------------------------------------------------
__global__ void __launch_bounds__(256, 2) __cluster_dims__(1, CPB, 1)
k_fuse(const float* __restrict__ fm, float* __restrict__ out)
{
    __shared__ float4 sp4[8 * 16];       // per-warp score partials (2 KB)
    __shared__ float4 sarr4[PX / 4];
    __shared__ float4 e4s [PX / 4];
    __shared__ float  m_sh;
    __shared__ float  ctxp[CC * 17];     // stride-17: conflict-free STS & LDS
    __shared__ float  cacc[CC];          // this CTA's merged ctx partials
    __shared__ float  st_m, st_s;        // this CTA's merged stats
    __shared__ float  w_s[CPB];
    __shared__ float  inv_sh;
    float* s_arr = reinterpret_cast<float*>(sarr4);
    float* e_sh  = reinterpret_cast<float*>(e4s);

    cg::cluster_group cl = cg::this_cluster();

    const int b    = blockIdx.x;
    const int cy   = blockIdx.y;         // cluster rank, 0..7
    const int t    = threadIdx.x;        // 256
    const int pj   = t & 15;             // pixel float4-group (coalescing key)
    const int ch0  = t >> 4;             // channel residue mod 16
    const int wid  = t >> 5;
    const int lane = t & 31;

    const float4* fm4 = reinterpret_cast<const float4*>(fm + (size_t)b * CC * HWN);

    // v slice for this thread's 16 channels: constant across all tiles
    float vc[16];
#pragma unroll
    for (int u = 0; u < 16; ++u)
        vc[u] = __ldg(&g_v[b * CC + ch0 + u * 16]);

    // running merged state (m_run uniform across threads; s_run owned by t0)
    float m_run = -3.0e38f;
    float s_run = 0.f;
    float acc   = 0.f;                   // channel t's merged context partial

    for (int j = 0; j < TPC; ++j) {
        const int blk = cy * TPC + j;
        const int p4  = blk * (PX / 4) + pj;

        // ---- load 16 channel-rows into registers (MLP 16) ----
        float4 f[16];
#pragma unroll
        for (int u = 0; u < 16; ++u)
            f[u] = fm4[(ch0 + u * 16) * (HWN / 4) + p4];

        // ---- score partial from registers ----
        float4 part = make_float4(0.f, 0.f, 0.f, 0.f);
#pragma unroll
        for (int u = 0; u < 16; ++u) {
            part.x += f[u].x * vc[u]; part.y += f[u].y * vc[u];
            part.z += f[u].z * vc[u]; part.w += f[u].w * vc[u];
        }
        // lanes L and L+16 share pj -> pair-reduce in warp
        part.x += __shfl_xor_sync(0xffffffffu, part.x, 16);
        part.y += __shfl_xor_sync(0xffffffffu, part.y, 16);
        part.z += __shfl_xor_sync(0xffffffffu, part.z, 16);
        part.w += __shfl_xor_sync(0xffffffffu, part.w, 16);

        if (lane < 16) sp4[wid * 16 + pj] = part;
        __syncthreads();                               // B

        if (t < 16) {
            float4 s = sp4[t];
#pragma unroll
            for (int w = 1; w < 8; ++w) {
                float4 x = sp4[w * 16 + t];
                s.x += x.x; s.y += x.y; s.z += x.z; s.w += x.w;
            }
            sarr4[t] = s;
        }
        __syncthreads();                               // C

        if (t < 32) {
            float m = fmaxf(s_arr[t], s_arr[t + 32]);
#pragma unroll
            for (int o = 16; o; o >>= 1)
                m = fmaxf(m, __shfl_xor_sync(0xffffffffu, m, o));
            if (t == 0) m_sh = m;
        }
        __syncthreads();                               // D
        const float Mt = m_sh;                         // tile-local max

        if (t < PX) e_sh[t] = expf(s_arr[t] - Mt);
        __syncthreads();                               // E

        const float4 e4 = e4s[pj];

        // merge scalars (uniform): so = exp(m_run - Mn), sn = exp(Mt - Mn)
        const float Mn = fmaxf(m_run, Mt);
        const float so = expf(m_run - Mt > 0.f ? 0.f : m_run - Mn);
        const float sn = expf(Mt - Mn);

        if (t < 32) {
            float s = e_sh[t] + e_sh[t + 32];
#pragma unroll
            for (int o = 16; o; o >>= 1)
                s += __shfl_xor_sync(0xffffffffu, s, o);
            if (t == 0) s_run = s_run * so + s * sn;
        }

        // ---- ctx partials straight from registers ----
#pragma unroll
        for (int u = 0; u < 16; ++u) {
            const float d = f[u].x * e4.x + f[u].y * e4.y
                          + f[u].z * e4.z + f[u].w * e4.w;
            ctxp[(ch0 + u * 16) * 17 + pj] = d;
        }
        __syncthreads();                               // F

        {
            float d = 0.f;
#pragma unroll
            for (int q = 0; q < 16; ++q) d += ctxp[t * 17 + q];
            acc = acc * so + d * sn;
        }
        m_run = Mn;
        // no trailing barrier: next iter's barrier B fences sp4/ctxp reuse
    }

    // ---- publish to cluster-visible SMEM ----
    cacc[t] = acc;
    if (t == 0) { st_m = m_run; st_s = s_run; }
    cl.sync();

    // ---- global stats over the 8 cluster CTAs (redundant in each CTA) ----
    if (t < CPB) {
        const float* pm = cl.map_shared_rank(&st_m, t);
        const float* ps = cl.map_shared_rank(&st_s, t);
        const float mloc = *pm;
        const float sloc = *ps;
        float M = mloc;
#pragma unroll
        for (int o = 4; o; o >>= 1)
            M = fmaxf(M, __shfl_xor_sync(0x000000ffu, M, o));
        const float w = expf(mloc - M);
        w_s[t] = w;
        float d = sloc * w;
#pragma unroll
        for (int o = 4; o; o >>= 1)
            d += __shfl_xor_sync(0x000000ffu, d, o);
        if (t == 0) inv_sh = 1.f / d;
    }
    __syncthreads();
    const float inv = inv_sh;

    // ---- each CTA writes its 32 output channels from peers' DSMEM ----
    if (t < 32) {
        float fin = 0.f;
#pragma unroll
        for (int p = 0; p < CPB; ++p) {
            const float* pc = cl.map_shared_rank(cacc, p);
            fin += pc[cy * 32 + t] * w_s[p];
        }
        out[b * CC + cy * 32 + t] = fin * inv;
    }

    cl.sync();   // keep SMEM alive until all peer reads complete
}

// ---------------------------------------------------------------------------
// Launch: two graph nodes total.
// ---------------------------------------------------------------------------
extern "C" void kernel_launch(void* const* d_in, const int* in_sizes, int n_in,
                              void* d_out, int out_size)
{
    const float* h_dec = nullptr;
    const float* fm    = nullptr;
    const float* W_fm  = nullptr;
    const float* W_h   = nullptr;
    const float* b_h   = nullptr;
    const float* biases[2] = {nullptr, nullptr};
    int nb = 0;

    for (int i = 0; i < n_in; ++i) {
        switch (in_sizes[i]) {
            case BB * HSZ:      h_dec = (const float*)d_in[i]; break;   // 16384
            case BB * CC * HWN: fm    = (const float*)d_in[i]; break;   // 33554432
            case CC * AA:       W_fm  = (const float*)d_in[i]; break;   // 65536
            case HSZ * AA:      W_h   = (const float*)d_in[i]; break;   // 131072
            case AA:            if (nb < 2) biases[nb++] = (const float*)d_in[i]; break;
            default: break;
        }
    }
    b_h = biases[1];   // metadata order: b_fm first (unused), b_h second

    float* out = (float*)d_out;

    k_front<<<BB,           256>>>(h_dec, W_h, W_fm, b_h);
    k_fuse <<<dim3(BB, CPB), 256>>>(fm, out);
}